// round 5
// baseline (speedup 1.0000x reference)
#include <cuda_runtime.h>
#include <math.h>
#include <stdint.h>

// ---------------------------------------------------------------------------
// TPAttention: x@Wq/Wk/Wv -> RoPE -> GQA flash attention over KV cache -> @Wo
// B=8 S=4 P=4096 HID=4096 HQ=32 HKV=8 D=128 (M=32). fp32 math, f32x2 FMA.
// ---------------------------------------------------------------------------

namespace {
constexpr int cB = 8, cS = 4, cP = 4096, cHQ = 32, cHKV = 8, cD = 128;
constexpr int cM = cB * cS;             // 32
constexpr int cK = 4096;
constexpr int cNQ = cHQ * cD;           // 4096
constexpr int cNKV = cHKV * cD;         // 1024
constexpr int cNTOT = cNQ + 2 * cNKV;   // 6144
constexpr int cT = cP + cS;             // 4100
constexpr int KSPLIT = 4;
constexpr int KCHUNK = cK / KSPLIT;     // 1024
constexpr int NSPLIT = 8;               // flash-decoding KV splits
constexpr int KBLK = 32;                // keys per tile (cp.async stage)
constexpr int NKB = (cT + KBLK - 1) / KBLK;        // 129
constexpr int KBPS = (NKB + NSPLIT - 1) / NSPLIT;  // 17
// smem: qs[16*128] + ks[2][32*132] + vs[2][32*132] + ps[16*36]
constexpr int ATTN_SMEM = (16 * 128 + 4 * 32 * 132 + 16 * 36) * 4;  // 78080
}  // namespace

typedef unsigned long long ull;

__device__ __forceinline__ ull pack2(float lo, float hi) {
  ull r;
  asm("mov.b64 %0, {%1, %2};" : "=l"(r) : "f"(lo), "f"(hi));
  return r;
}
__device__ __forceinline__ float2 unpack2(ull v) {
  float2 f;
  asm("mov.b64 {%0, %1}, %2;" : "=f"(f.x), "=f"(f.y) : "l"(v));
  return f;
}
__device__ __forceinline__ void ffma2(ull& d, ull a, ull b) {
  asm("fma.rn.f32x2 %0, %1, %2, %0;" : "+l"(d) : "l"(a), "l"(b));
}
__device__ __forceinline__ ull fmul2(ull a, ull b) {
  ull r;
  asm("mul.rn.f32x2 %0, %1, %2;" : "=l"(r) : "l"(a), "l"(b));
  return r;
}
__device__ __forceinline__ void cpa16(uint32_t s, const void* g) {
  asm volatile("cp.async.cg.shared.global [%0], [%1], 16;" :: "r"(s), "l"(g));
}
__device__ __forceinline__ void cpa_commit() {
  asm volatile("cp.async.commit_group;");
}
template <int N>
__device__ __forceinline__ void cpa_wait() {
  asm volatile("cp.async.wait_group %0;" :: "n"(N));
}

__device__ float g_qkvp[KSPLIT][cM * cNTOT];
__device__ float g_q[cM * cHQ * cD];
__device__ float g_kn[cM * cHKV * cD];
__device__ float g_vn[cM * cHKV * cD];
__device__ float g_Op[cB * cHKV * NSPLIT * 16 * cD];
__device__ float g_Ms[cB * cHKV * NSPLIT * 16];
__device__ float g_Ls[cB * cHKV * NSPLIT * 16];
__device__ float g_ao[cM * cNQ];
__device__ float g_outp[KSPLIT][cM * cNQ];

// ---------------------------------------------------------------------------
// GEMM (f32x2): C_split = A[32 x 4096] @ W, 64-col N tiles, split-K grid.y.
// k-step 32, register-prefetch double-buffered smem. (unchanged from R4)
// ---------------------------------------------------------------------------
__global__ __launch_bounds__(128) void gemm_f2_kernel(
    const float* __restrict__ A, const float* __restrict__ W0,
    const float* __restrict__ W1, const float* __restrict__ W2,
    float* __restrict__ Cb, int qkv) {
  __shared__ float xs[2][32][36];
  __shared__ float ws[2][32][68];
  const int tid = threadIdx.x;
  const int bx = blockIdx.x;

  const float* W;
  int ldw, ncol, ldc, csz;
  if (qkv) {
    ldc = cNTOT; csz = cM * cNTOT;
    if (bx < 64)      { W = W0; ldw = cNQ;  ncol = bx * 64; }
    else if (bx < 80) { W = W1; ldw = cNKV; ncol = cNQ + (bx - 64) * 64; }
    else              { W = W2; ldw = cNKV; ncol = cNQ + cNKV + (bx - 80) * 64; }
  } else {
    ldc = cNQ; csz = cM * cNQ;
    W = W0; ldw = cNQ; ncol = bx * 64;
  }
  const int n0w = (qkv ? (ncol - (bx < 64 ? 0 : (bx < 80 ? cNQ : cNQ + cNKV)))
                       : ncol);
  const int k0s = blockIdx.y * KCHUNK;
  float* C = Cb + blockIdx.y * csz;

  const int mg = tid >> 4;
  const int ng = tid & 15;
  const int lm = tid >> 2;
  const int lkv = tid & 3;
  const int wk0 = tid >> 4;
  const int wn = tid & 15;
  const int wgcol = n0w + 4 * wn;

  ull acc[4][2] = {};

  float4 xr0 = *(const float4*)&A[lm * cK + k0s + 4 * lkv];
  float4 xr1 = *(const float4*)&A[lm * cK + k0s + 16 + 4 * lkv];
  float4 wr[4];
#pragma unroll
  for (int q = 0; q < 4; q++)
    wr[q] = *(const float4*)&W[(k0s + wk0 + 8 * q) * ldw + wgcol];

#pragma unroll
  for (int c = 0; c < 4; c++) {
    xs[0][4 * lkv + c][lm] = (&xr0.x)[c];
    xs[0][16 + 4 * lkv + c][lm] = (&xr1.x)[c];
  }
#pragma unroll
  for (int q = 0; q < 4; q++) *(float4*)&ws[0][wk0 + 8 * q][4 * wn] = wr[q];
  __syncthreads();

  const int NT = KCHUNK / 32;
  for (int t = 0; t < NT; t++) {
    const int st = t & 1;
    const bool more = (t + 1 < NT);
    if (more) {
      const int k1 = k0s + 32 * (t + 1);
      xr0 = *(const float4*)&A[lm * cK + k1 + 4 * lkv];
      xr1 = *(const float4*)&A[lm * cK + k1 + 16 + 4 * lkv];
#pragma unroll
      for (int q = 0; q < 4; q++)
        wr[q] = *(const float4*)&W[(k1 + wk0 + 8 * q) * ldw + wgcol];
    }
#pragma unroll
    for (int kk = 0; kk < 32; kk++) {
      const float4 xv = *(const float4*)&xs[st][kk][4 * mg];
      const ulonglong2 wv = *(const ulonglong2*)&ws[st][kk][4 * ng];
      const ull x0 = pack2(xv.x, xv.x);
      const ull x1 = pack2(xv.y, xv.y);
      const ull x2 = pack2(xv.z, xv.z);
      const ull x3 = pack2(xv.w, xv.w);
      ffma2(acc[0][0], x0, wv.x); ffma2(acc[0][1], x0, wv.y);
      ffma2(acc[1][0], x1, wv.x); ffma2(acc[1][1], x1, wv.y);
      ffma2(acc[2][0], x2, wv.x); ffma2(acc[2][1], x2, wv.y);
      ffma2(acc[3][0], x3, wv.x); ffma2(acc[3][1], x3, wv.y);
    }
    if (more) {
      const int s2 = st ^ 1;
#pragma unroll
      for (int c = 0; c < 4; c++) {
        xs[s2][4 * lkv + c][lm] = (&xr0.x)[c];
        xs[s2][16 + 4 * lkv + c][lm] = (&xr1.x)[c];
      }
#pragma unroll
      for (int q = 0; q < 4; q++) *(float4*)&ws[s2][wk0 + 8 * q][4 * wn] = wr[q];
    }
    __syncthreads();
  }

#pragma unroll
  for (int i = 0; i < 4; i++) {
    const float2 lo = unpack2(acc[i][0]);
    const float2 hi = unpack2(acc[i][1]);
    float4 o = make_float4(lo.x, lo.y, hi.x, hi.y);
    *(float4*)&C[(4 * mg + i) * ldc + ncol + 4 * ng] = o;
  }
}

// ---------------------------------------------------------------------------
// Reduce split-K partials of qkv, apply RoPE to q/k, scatter to buffers.
// ---------------------------------------------------------------------------
__global__ __launch_bounds__(256) void rope_kernel(
    const float* __restrict__ cosb, const float* __restrict__ sinb,
    const int* __restrict__ past_len) {
  const int i = blockIdx.x * 256 + threadIdx.x;
  if (i >= cM * cNTOT) return;
  const int m = i / cNTOT, c = i - m * cNTOT;
  const int s = m & 3;
  const float val = g_qkvp[0][i] + g_qkvp[1][i] + g_qkvp[2][i] + g_qkvp[3][i];
  const int pos = past_len[0] + s;
  if (c < cNQ) {
    const int hq = c >> 7, d = c & 127;
    const int io = m * cNTOT + (c ^ 64);
    const float oth = g_qkvp[0][io] + g_qkvp[1][io] + g_qkvp[2][io] + g_qkvp[3][io];
    const float rot = (d < 64) ? -oth : oth;
    g_q[(m * cHQ + hq) * cD + d] =
        fmaf(val, cosb[pos * cD + d], rot * sinb[pos * cD + d]);
  } else if (c < cNQ + cNKV) {
    const int cc = c - cNQ;
    const int hk = cc >> 7, d = cc & 127;
    const int io = m * cNTOT + cNQ + (cc ^ 64);
    const float oth = g_qkvp[0][io] + g_qkvp[1][io] + g_qkvp[2][io] + g_qkvp[3][io];
    const float rot = (d < 64) ? -oth : oth;
    g_kn[(m * cHKV + hk) * cD + d] =
        fmaf(val, cosb[pos * cD + d], rot * sinb[pos * cD + d]);
  } else {
    const int cc = c - cNQ - cNKV;
    g_vn[(m * cHKV + (cc >> 7)) * cD + (cc & 127)] = val;
  }
}

// ---------------------------------------------------------------------------
// Flash-decoding attention, cp.async double-buffered (KBLK=32, 2 stages).
// Grid (64 bh, NSPLIT=8). 256 threads = 8 warps; warp w owns rows 2w, 2w+1.
// Score: lane = key. PV: lane = d-chunk. Softmax state in registers.
// 4 warps/SMSP (2 CTAs/SM) hides shfl/MUFU latency.
// ---------------------------------------------------------------------------
__global__ __launch_bounds__(256) void attn_kernel(
    const float* __restrict__ kc, const float* __restrict__ vc,
    const int* __restrict__ past_len) {
  extern __shared__ float sm[];
  float* qs = sm;                    // [16][128]
  float* ks = qs + 16 * 128;         // [2][32][132]
  float* vs = ks + 2 * 32 * 132;     // [2][32][132]
  float* ps = vs + 2 * 32 * 132;     // [16][36]

  const int tid = threadIdx.x;
  const int bh = blockIdx.x;
  const int b = bh >> 3, h = bh & 7;
  const int split = blockIdx.y;
  const int pl = past_len[0];
  const float scale = 0.08838834764831845f;  // 1/sqrt(128)
  const int wid = tid >> 5;  // warp 0..7: rows 2*wid, 2*wid+1
  const int kg = tid & 31;   // key lane / d lane

#pragma unroll
  for (int it = 0; it < 2; it++) {
    const int idx = tid + it * 256;  // 0..511
    const int r = idx >> 5, dv = idx & 31;
    const int s = r >> 2, g = r & 3;
    float4 qv = *(const float4*)&g_q[((b * cS + s) * cHQ + (h * 4 + g)) * cD + 4 * dv];
    qv.x *= scale; qv.y *= scale; qv.z *= scale; qv.w *= scale;
    *(float4*)&qs[r * 128 + 4 * dv] = qv;
  }

  const uint32_t ks_base = (uint32_t)__cvta_generic_to_shared(ks);
  const uint32_t vs_base = (uint32_t)__cvta_generic_to_shared(vs);

  const int kb0 = split * KBPS;
  const int kb1 = (kb0 + KBPS < NKB) ? (kb0 + KBPS) : NKB;
  const int ntiles = kb1 - kb0;

  auto load_tile = [&](int kb, int st) {
    const int t0 = kb * KBLK;
    const uint32_t kdst0 = ks_base + (uint32_t)(st * 32 * 132 * 4);
    const uint32_t vdst0 = vs_base + (uint32_t)(st * 32 * 132 * 4);
#pragma unroll
    for (int it = 0; it < 4; it++) {
      const int idx = tid + it * 256;       // 0..1023
      const int tt = idx >> 5, dv = idx & 31;
      int t = t0 + tt;
      if (t > cT - 1) t = cT - 1;           // clamp tail (finite; masked)
      const float *ksrc, *vsrc;
      if (t < cP) {
        const int off = ((b * cP + t) * cHKV + h) * cD + 4 * dv;
        ksrc = kc + off; vsrc = vc + off;
      } else {
        const int off = ((b * cS + (t - cP)) * cHKV + h) * cD + 4 * dv;
        ksrc = g_kn + off; vsrc = g_vn + off;
      }
      const uint32_t so = (uint32_t)((tt * 132 + 4 * dv) * 4);
      cpa16(kdst0 + so, ksrc);
      cpa16(vdst0 + so, vsrc);
    }
  };

  float mrun[2] = {-1e30f, -1e30f};
  float lrun[2] = {0.f, 0.f};
  ull o2[2][2] = {};

  load_tile(kb0, 0);
  cpa_commit();

  for (int i = 0; i < ntiles; i++) {
    const int st = i & 1;
    const int t0 = (kb0 + i) * KBLK;
    const bool more = (i + 1 < ntiles);
    if (more) {
      load_tile(kb0 + i + 1, st ^ 1);
      cpa_commit();
      cpa_wait<1>();
    } else {
      cpa_wait<0>();
    }
    __syncthreads();

    const float* kst = ks + st * 32 * 132;
    const float* vst = vs + st * 32 * 132;

    // ---- scores: 2 rows x 1 key (lane) per thread, 2 chains per row ----
    ull sa[2] = {}, sb[2] = {};
#pragma unroll 8
    for (int dv = 0; dv < 32; dv++) {
      const ulonglong2 kv = *(const ulonglong2*)&kst[kg * 132 + 4 * dv];
#pragma unroll
      for (int j = 0; j < 2; j++) {
        const ulonglong2 qv = *(const ulonglong2*)&qs[(2 * wid + j) * 128 + 4 * dv];
        ffma2(sa[j], qv.x, kv.x);
        ffma2(sb[j], qv.y, kv.y);
      }
    }

    float fac[2];
#pragma unroll
    for (int j = 0; j < 2; j++) {
      const int r = 2 * wid + j;
      const int sidx = r >> 2;
      const float2 a = unpack2(sa[j]);
      const float2 c = unpack2(sb[j]);
      float s0 = (a.x + a.y) + (c.x + c.y);
      if (t0 + kg > pl + sidx) s0 = -1e30f;   // causal + tail mask
      float mx = s0;
#pragma unroll
      for (int w = 16; w; w >>= 1) mx = fmaxf(mx, __shfl_xor_sync(0xffffffffu, mx, w));
      const float mnew = fmaxf(mrun[j], mx);
      const float f = __expf(mrun[j] - mnew);
      const float p0 = (s0 < -1e29f) ? 0.f : __expf(s0 - mnew);
      ps[r * 36 + kg] = p0;
      float ls = p0;
#pragma unroll
      for (int w = 16; w; w >>= 1) ls += __shfl_xor_sync(0xffffffffu, ls, w);
      lrun[j] = fmaf(lrun[j], f, ls);
      mrun[j] = mnew;
      fac[j] = f;
    }
    __syncwarp();

    // ---- P @ V: 2 rows x d-chunk float4 per thread ----
#pragma unroll
    for (int j = 0; j < 2; j++) {
      const ull ff = pack2(fac[j], fac[j]);
      o2[j][0] = fmul2(o2[j][0], ff);
      o2[j][1] = fmul2(o2[j][1], ff);
    }
#pragma unroll
    for (int tt = 0; tt < KBLK; tt += 4) {
      float4 p4[2];
#pragma unroll
      for (int j = 0; j < 2; j++)
        p4[j] = *(const float4*)&ps[(2 * wid + j) * 36 + tt];
#pragma unroll
      for (int u = 0; u < 4; u++) {
        const ulonglong2 vv = *(const ulonglong2*)&vst[(tt + u) * 132 + 4 * kg];
#pragma unroll
        for (int j = 0; j < 2; j++) {
          const float p = (&p4[j].x)[u];
          const ull pp = pack2(p, p);
          ffma2(o2[j][0], pp, vv.x);
          ffma2(o2[j][1], pp, vv.y);
        }
      }
    }
    __syncthreads();
  }

  const int base = (bh * NSPLIT + split) * 16;
#pragma unroll
  for (int j = 0; j < 2; j++) {
    const int r = 2 * wid + j;
    const float2 lo = unpack2(o2[j][0]);
    const float2 hi = unpack2(o2[j][1]);
    float4 o = make_float4(lo.x, lo.y, hi.x, hi.y);
    *(float4*)&g_Op[(base + r) * cD + 4 * kg] = o;
  }
  if (kg == 0) {
#pragma unroll
    for (int j = 0; j < 2; j++) {
      g_Ms[base + 2 * wid + j] = mrun[j];
      g_Ls[base + 2 * wid + j] = lrun[j];
    }
  }
}

// ---------------------------------------------------------------------------
// Combine KV splits -> attention output buffer.
// ---------------------------------------------------------------------------
__global__ __launch_bounds__(256) void combine_kernel() {
  const int bh = blockIdx.x, tid = threadIdx.x;
  const int r = tid >> 4;
  const int dq = (tid & 15) * 8;
  const int b = bh >> 3, h = bh & 7;
  const int base = bh * NSPLIT;
  float m[NSPLIT], l[NSPLIT];
  float mstar = -1e30f;
#pragma unroll
  for (int i = 0; i < NSPLIT; i++) {
    m[i] = g_Ms[(base + i) * 16 + r];
    l[i] = g_Ls[(base + i) * 16 + r];
    mstar = fmaxf(mstar, m[i]);
  }
  float w[NSPLIT];
  float L = 0.f;
#pragma unroll
  for (int i = 0; i < NSPLIT; i++) {
    w[i] = __expf(m[i] - mstar);
    L = fmaf(w[i], l[i], L);
  }
  const float inv = 1.f / L;
  const int s = r >> 2, g = r & 3;
  float* dst = &g_ao[((b * cS + s) * cHQ + (h * 4 + g)) * cD + dq];
#pragma unroll
  for (int c2 = 0; c2 < 2; c2++) {
    float4 a = make_float4(0.f, 0.f, 0.f, 0.f);
#pragma unroll
    for (int i = 0; i < NSPLIT; i++) {
      const float4 ov = *(const float4*)&g_Op[((base + i) * 16 + r) * cD + dq + 4 * c2];
      a.x = fmaf(w[i], ov.x, a.x);
      a.y = fmaf(w[i], ov.y, a.y);
      a.z = fmaf(w[i], ov.z, a.z);
      a.w = fmaf(w[i], ov.w, a.w);
    }
    a.x *= inv; a.y *= inv; a.z *= inv; a.w *= inv;
    *(float4*)&dst[4 * c2] = a;
  }
}

// ---------------------------------------------------------------------------
__global__ __launch_bounds__(256) void sum_out_kernel(float* __restrict__ out) {
  const int i = blockIdx.x * 256 + threadIdx.x;
  if (i < cM * cNQ)
    out[i] = g_outp[0][i] + g_outp[1][i] + g_outp[2][i] + g_outp[3][i];
}

// ---------------------------------------------------------------------------
extern "C" void kernel_launch(void* const* d_in, const int* in_sizes, int n_in,
                              void* d_out, int out_size) {
  const float* x = (const float*)d_in[0];
  const float* wq = (const float*)d_in[1];
  const float* wk = (const float*)d_in[2];
  const float* wv = (const float*)d_in[3];
  const float* wo = (const float*)d_in[4];
  const float* cosb = (const float*)d_in[5];
  const float* sinb = (const float*)d_in[6];
  const float* kc = (const float*)d_in[7];
  const float* vc = (const float*)d_in[8];
  const int* pl = (const int*)d_in[9];
  float* out = (float*)d_out;

  float *qkvp, *aop, *outp;
  cudaGetSymbolAddress((void**)&qkvp, g_qkvp);
  cudaGetSymbolAddress((void**)&aop, g_ao);
  cudaGetSymbolAddress((void**)&outp, g_outp);

  // Combined QKV projection (split-K partials): 64 q-tiles + 16 k + 16 v
  gemm_f2_kernel<<<dim3(96, KSPLIT), 128>>>(x, wq, wk, wv, qkvp, 1);
  // reduce + RoPE
  rope_kernel<<<(cM * cNTOT + 255) / 256, 256>>>(cosb, sinb, pl);
  // flash-decoding attention (cp.async pipelined, 8 splits, 8 warps/CTA)
  cudaFuncSetAttribute(attn_kernel, cudaFuncAttributeMaxDynamicSharedMemorySize, ATTN_SMEM);
  attn_kernel<<<dim3(cB * cHKV, NSPLIT), 256, ATTN_SMEM>>>(kc, vc, pl);
  combine_kernel<<<cB * cHKV, 256>>>();
  // output projection
  gemm_f2_kernel<<<dim3(64, KSPLIT), 128>>>(aop, wo, wo, wo, outp, 0);
  sum_out_kernel<<<(cM * cNQ + 255) / 256, 256>>>(out);
}

// round 6
// speedup vs baseline: 1.0258x; 1.0258x over previous
#include <cuda_runtime.h>
#include <math.h>
#include <stdint.h>

// ---------------------------------------------------------------------------
// TPAttention: x@Wq/Wk/Wv -> RoPE -> GQA flash attention over KV cache -> @Wo
// B=8 S=4 P=4096 HID=4096 HQ=32 HKV=8 D=128 (M=32). fp32 math, f32x2 FMA.
// ---------------------------------------------------------------------------

namespace {
constexpr int cB = 8, cS = 4, cP = 4096, cHQ = 32, cHKV = 8, cD = 128;
constexpr int cM = cB * cS;             // 32
constexpr int cK = 4096;
constexpr int cNQ = cHQ * cD;           // 4096
constexpr int cNKV = cHKV * cD;         // 1024
constexpr int cNTOT = cNQ + 2 * cNKV;   // 6144
constexpr int cT = cP + cS;             // 4100
constexpr int KSPLIT = 4;
constexpr int KCHUNK = cK / KSPLIT;     // 1024
constexpr int NSPLIT = 4;               // flash-decoding KV splits
constexpr int KBLK = 32;                // keys per tile (cp.async stage)
constexpr int NSTG = 3;                 // cp.async stages
constexpr int NKB = (cT + KBLK - 1) / KBLK;        // 129
constexpr int KBPS = (NKB + NSPLIT - 1) / NSPLIT;  // 33
// smem: qs[16*128] + ks[3][32][132] + vs[3][32][132] + ps[16][36]
constexpr int ATTN_SMEM = (16 * 128 + 2 * NSTG * 32 * 132 + 16 * 36) * 4;  // 111872
}  // namespace

typedef unsigned long long ull;

__device__ __forceinline__ ull pack2(float lo, float hi) {
  ull r;
  asm("mov.b64 %0, {%1, %2};" : "=l"(r) : "f"(lo), "f"(hi));
  return r;
}
__device__ __forceinline__ float2 unpack2(ull v) {
  float2 f;
  asm("mov.b64 {%0, %1}, %2;" : "=f"(f.x), "=f"(f.y) : "l"(v));
  return f;
}
__device__ __forceinline__ void ffma2(ull& d, ull a, ull b) {
  asm("fma.rn.f32x2 %0, %1, %2, %0;" : "+l"(d) : "l"(a), "l"(b));
}
__device__ __forceinline__ ull fmul2(ull a, ull b) {
  ull r;
  asm("mul.rn.f32x2 %0, %1, %2;" : "=l"(r) : "l"(a), "l"(b));
  return r;
}
__device__ __forceinline__ void cpa16(uint32_t s, const void* g) {
  asm volatile("cp.async.cg.shared.global [%0], [%1], 16;" :: "r"(s), "l"(g));
}
__device__ __forceinline__ void cpa_commit() {
  asm volatile("cp.async.commit_group;");
}
template <int N>
__device__ __forceinline__ void cpa_wait() {
  asm volatile("cp.async.wait_group %0;" :: "n"(N));
}

__device__ float g_qkvp[KSPLIT][cM * cNTOT];
__device__ float g_q[cM * cHQ * cD];
__device__ float g_kn[cM * cHKV * cD];
__device__ float g_vn[cM * cHKV * cD];
__device__ float g_Op[cB * cHKV * NSPLIT * 16 * cD];
__device__ float g_Ms[cB * cHKV * NSPLIT * 16];
__device__ float g_Ls[cB * cHKV * NSPLIT * 16];
__device__ float g_ao[cM * cNQ];
__device__ float g_outp[KSPLIT][cM * cNQ];

// ---------------------------------------------------------------------------
// GEMM (f32x2): C_split = A[32 x 4096] @ W, 64-col N tiles, split-K grid.y.
// x staged in smem as pre-duplicated f32x2 pairs -> no pack MOVs inner loop.
// ---------------------------------------------------------------------------
__global__ __launch_bounds__(128) void gemm_f2_kernel(
    const float* __restrict__ A, const float* __restrict__ W0,
    const float* __restrict__ W1, const float* __restrict__ W2,
    float* __restrict__ Cb, int qkv) {
  __shared__ ull xs2[2][32][34];    // [stage][kk][m] duplicated pairs
  __shared__ float ws[2][32][68];
  const int tid = threadIdx.x;
  const int bx = blockIdx.x;

  const float* W;
  int ldw, ncol, ldc, csz;
  if (qkv) {
    ldc = cNTOT; csz = cM * cNTOT;
    if (bx < 64)      { W = W0; ldw = cNQ;  ncol = bx * 64; }
    else if (bx < 80) { W = W1; ldw = cNKV; ncol = cNQ + (bx - 64) * 64; }
    else              { W = W2; ldw = cNKV; ncol = cNQ + cNKV + (bx - 80) * 64; }
  } else {
    ldc = cNQ; csz = cM * cNQ;
    W = W0; ldw = cNQ; ncol = bx * 64;
  }
  const int n0w = (qkv ? (ncol - (bx < 64 ? 0 : (bx < 80 ? cNQ : cNQ + cNKV)))
                       : ncol);
  const int k0s = blockIdx.y * KCHUNK;
  float* C = Cb + blockIdx.y * csz;

  const int mg = tid >> 4;
  const int ng = tid & 15;
  const int lm = tid >> 2;
  const int lkv = tid & 3;
  const int wk0 = tid >> 4;
  const int wn = tid & 15;
  const int wgcol = n0w + 4 * wn;

  ull acc[4][2] = {};

  float4 xr0 = *(const float4*)&A[lm * cK + k0s + 4 * lkv];
  float4 xr1 = *(const float4*)&A[lm * cK + k0s + 16 + 4 * lkv];
  float4 wr[4];
#pragma unroll
  for (int q = 0; q < 4; q++)
    wr[q] = *(const float4*)&W[(k0s + wk0 + 8 * q) * ldw + wgcol];

#pragma unroll
  for (int c = 0; c < 4; c++) {
    xs2[0][4 * lkv + c][lm] = pack2((&xr0.x)[c], (&xr0.x)[c]);
    xs2[0][16 + 4 * lkv + c][lm] = pack2((&xr1.x)[c], (&xr1.x)[c]);
  }
#pragma unroll
  for (int q = 0; q < 4; q++) *(float4*)&ws[0][wk0 + 8 * q][4 * wn] = wr[q];
  __syncthreads();

  const int NT = KCHUNK / 32;
  for (int t = 0; t < NT; t++) {
    const int st = t & 1;
    const bool more = (t + 1 < NT);
    if (more) {
      const int k1 = k0s + 32 * (t + 1);
      xr0 = *(const float4*)&A[lm * cK + k1 + 4 * lkv];
      xr1 = *(const float4*)&A[lm * cK + k1 + 16 + 4 * lkv];
#pragma unroll
      for (int q = 0; q < 4; q++)
        wr[q] = *(const float4*)&W[(k1 + wk0 + 8 * q) * ldw + wgcol];
    }
#pragma unroll
    for (int kk = 0; kk < 32; kk++) {
      const ulonglong2 xa = *(const ulonglong2*)&xs2[st][kk][4 * mg];
      const ulonglong2 xb = *(const ulonglong2*)&xs2[st][kk][4 * mg + 2];
      const ulonglong2 wv = *(const ulonglong2*)&ws[st][kk][4 * ng];
      ffma2(acc[0][0], xa.x, wv.x); ffma2(acc[0][1], xa.x, wv.y);
      ffma2(acc[1][0], xa.y, wv.x); ffma2(acc[1][1], xa.y, wv.y);
      ffma2(acc[2][0], xb.x, wv.x); ffma2(acc[2][1], xb.x, wv.y);
      ffma2(acc[3][0], xb.y, wv.x); ffma2(acc[3][1], xb.y, wv.y);
    }
    if (more) {
      const int s2 = st ^ 1;
#pragma unroll
      for (int c = 0; c < 4; c++) {
        xs2[s2][4 * lkv + c][lm] = pack2((&xr0.x)[c], (&xr0.x)[c]);
        xs2[s2][16 + 4 * lkv + c][lm] = pack2((&xr1.x)[c], (&xr1.x)[c]);
      }
#pragma unroll
      for (int q = 0; q < 4; q++) *(float4*)&ws[s2][wk0 + 8 * q][4 * wn] = wr[q];
    }
    __syncthreads();
  }

#pragma unroll
  for (int i = 0; i < 4; i++) {
    const float2 lo = unpack2(acc[i][0]);
    const float2 hi = unpack2(acc[i][1]);
    float4 o = make_float4(lo.x, lo.y, hi.x, hi.y);
    *(float4*)&C[(4 * mg + i) * ldc + ncol + 4 * ng] = o;
  }
}

// ---------------------------------------------------------------------------
// Reduce split-K partials of qkv, apply RoPE to q/k, scatter to buffers.
// ---------------------------------------------------------------------------
__global__ __launch_bounds__(256) void rope_kernel(
    const float* __restrict__ cosb, const float* __restrict__ sinb,
    const int* __restrict__ past_len) {
  const int i = blockIdx.x * 256 + threadIdx.x;
  if (i >= cM * cNTOT) return;
  const int m = i / cNTOT, c = i - m * cNTOT;
  const int s = m & 3;
  const float val = g_qkvp[0][i] + g_qkvp[1][i] + g_qkvp[2][i] + g_qkvp[3][i];
  const int pos = past_len[0] + s;
  if (c < cNQ) {
    const int hq = c >> 7, d = c & 127;
    const int io = m * cNTOT + (c ^ 64);
    const float oth = g_qkvp[0][io] + g_qkvp[1][io] + g_qkvp[2][io] + g_qkvp[3][io];
    const float rot = (d < 64) ? -oth : oth;
    g_q[(m * cHQ + hq) * cD + d] =
        fmaf(val, cosb[pos * cD + d], rot * sinb[pos * cD + d]);
  } else if (c < cNQ + cNKV) {
    const int cc = c - cNQ;
    const int hk = cc >> 7, d = cc & 127;
    const int io = m * cNTOT + cNQ + (cc ^ 64);
    const float oth = g_qkvp[0][io] + g_qkvp[1][io] + g_qkvp[2][io] + g_qkvp[3][io];
    const float rot = (d < 64) ? -oth : oth;
    g_kn[(m * cHKV + hk) * cD + d] =
        fmaf(val, cosb[pos * cD + d], rot * sinb[pos * cD + d]);
  } else {
    const int cc = c - cNQ - cNKV;
    g_vn[(m * cHKV + (cc >> 7)) * cD + (cc & 127)] = val;
  }
}

// ---------------------------------------------------------------------------
// Flash-decoding attention, 3-stage cp.async pipeline (KBLK=32).
// Grid (64 bh, NSPLIT=4). 128 threads = 4 warps; warp rg owns rows 4rg..4rg+3.
// Score: lane = key; softmax butterflies interleaved across the 4 rows.
// ---------------------------------------------------------------------------
__global__ __launch_bounds__(128) void attn_kernel(
    const float* __restrict__ kc, const float* __restrict__ vc,
    const int* __restrict__ past_len) {
  extern __shared__ float sm[];
  float* qs = sm;                         // [16][128]
  float* ks = qs + 16 * 128;              // [NSTG][32][132]
  float* vs = ks + NSTG * 32 * 132;       // [NSTG][32][132]
  float* ps = vs + NSTG * 32 * 132;       // [16][36]

  const int tid = threadIdx.x;
  const int bh = blockIdx.x;
  const int b = bh >> 3, h = bh & 7;
  const int split = blockIdx.y;
  const int pl = past_len[0];
  const float scale = 0.08838834764831845f;  // 1/sqrt(128)
  const int rg = tid >> 5;   // warp id = s index
  const int kg = tid & 31;   // key lane / d lane

#pragma unroll
  for (int it = 0; it < 4; it++) {
    const int idx = tid + it * 128;
    const int r = idx >> 5, dv = idx & 31;
    const int s = r >> 2, g = r & 3;
    float4 qv = *(const float4*)&g_q[((b * cS + s) * cHQ + (h * 4 + g)) * cD + 4 * dv];
    qv.x *= scale; qv.y *= scale; qv.z *= scale; qv.w *= scale;
    *(float4*)&qs[r * 128 + 4 * dv] = qv;
  }

  const uint32_t ks_base = (uint32_t)__cvta_generic_to_shared(ks);
  const uint32_t vs_base = (uint32_t)__cvta_generic_to_shared(vs);

  const int kb0 = split * KBPS;
  const int kb1 = (kb0 + KBPS < NKB) ? (kb0 + KBPS) : NKB;
  const int ntiles = kb1 - kb0;

  auto load_tile = [&](int kb, int st) {
    const int t0 = kb * KBLK;
    const uint32_t kdst0 = ks_base + (uint32_t)(st * 32 * 132 * 4);
    const uint32_t vdst0 = vs_base + (uint32_t)(st * 32 * 132 * 4);
#pragma unroll
    for (int it = 0; it < 8; it++) {
      const int idx = tid + it * 128;       // 0..1023
      const int tt = idx >> 5, dv = idx & 31;
      int t = t0 + tt;
      if (t > cT - 1) t = cT - 1;           // clamp tail (finite; masked)
      const float *ksrc, *vsrc;
      if (t < cP) {
        const int off = ((b * cP + t) * cHKV + h) * cD + 4 * dv;
        ksrc = kc + off; vsrc = vc + off;
      } else {
        const int off = ((b * cS + (t - cP)) * cHKV + h) * cD + 4 * dv;
        ksrc = g_kn + off; vsrc = g_vn + off;
      }
      const uint32_t so = (uint32_t)((tt * 132 + 4 * dv) * 4);
      cpa16(kdst0 + so, ksrc);
      cpa16(vdst0 + so, vsrc);
    }
  };

  float mrun[4] = {-1e30f, -1e30f, -1e30f, -1e30f};
  float lrun[4] = {0.f, 0.f, 0.f, 0.f};
  ull o2[4][2] = {};

  load_tile(kb0, 0);
  cpa_commit();
  if (ntiles > 1) {
    load_tile(kb0 + 1, 1);
    cpa_commit();
  }

  for (int i = 0; i < ntiles; i++) {
    const int st = i % NSTG;
    const int t0 = (kb0 + i) * KBLK;
    if (i + 2 < ntiles) {
      load_tile(kb0 + i + 2, (i + 2) % NSTG);
      cpa_commit();
      cpa_wait<2>();
    } else if (i + 1 < ntiles) {
      cpa_wait<1>();
    } else {
      cpa_wait<0>();
    }
    __syncthreads();

    const float* kst = ks + st * 32 * 132;
    const float* vst = vs + st * 32 * 132;

    // ---- scores: 4 rows x 1 key (lane) per thread, 2 chains per row ----
    ull sa[4] = {}, sb[4] = {};
#pragma unroll 8
    for (int dv = 0; dv < 32; dv++) {
      const ulonglong2 kv = *(const ulonglong2*)&kst[kg * 132 + 4 * dv];
#pragma unroll
      for (int j = 0; j < 4; j++) {
        const ulonglong2 qv = *(const ulonglong2*)&qs[(4 * rg + j) * 128 + 4 * dv];
        ffma2(sa[j], qv.x, kv.x);
        ffma2(sb[j], qv.y, kv.y);
      }
    }

    // masked scores
    float s0[4];
#pragma unroll
    for (int j = 0; j < 4; j++) {
      const float2 a = unpack2(sa[j]);
      const float2 c = unpack2(sb[j]);
      s0[j] = (a.x + a.y) + (c.x + c.y);
      if (t0 + kg > pl + rg) s0[j] = -1e30f;  // causal + tail mask
    }
    // step-major max butterfly (4 rows interleaved)
    float mx[4] = {s0[0], s0[1], s0[2], s0[3]};
#pragma unroll
    for (int w = 16; w; w >>= 1) {
#pragma unroll
      for (int j = 0; j < 4; j++)
        mx[j] = fmaxf(mx[j], __shfl_xor_sync(0xffffffffu, mx[j], w));
    }
    float fac[4], p[4], mnew[4];
#pragma unroll
    for (int j = 0; j < 4; j++) {
      mnew[j] = fmaxf(mrun[j], mx[j]);
      fac[j] = __expf(mrun[j] - mnew[j]);
      p[j] = (s0[j] < -1e29f) ? 0.f : __expf(s0[j] - mnew[j]);
      ps[(4 * rg + j) * 36 + kg] = p[j];
      mrun[j] = mnew[j];
    }
    // step-major sum butterfly
    float ls[4] = {p[0], p[1], p[2], p[3]};
#pragma unroll
    for (int w = 16; w; w >>= 1) {
#pragma unroll
      for (int j = 0; j < 4; j++)
        ls[j] += __shfl_xor_sync(0xffffffffu, ls[j], w);
    }
#pragma unroll
    for (int j = 0; j < 4; j++) lrun[j] = fmaf(lrun[j], fac[j], ls[j]);
    __syncwarp();

    // ---- P @ V: 4 rows x d-chunk float4 per thread ----
#pragma unroll
    for (int j = 0; j < 4; j++) {
      const ull ff = pack2(fac[j], fac[j]);
      o2[j][0] = fmul2(o2[j][0], ff);
      o2[j][1] = fmul2(o2[j][1], ff);
    }
#pragma unroll
    for (int tt = 0; tt < KBLK; tt += 4) {
      float4 p4[4];
#pragma unroll
      for (int j = 0; j < 4; j++)
        p4[j] = *(const float4*)&ps[(4 * rg + j) * 36 + tt];
#pragma unroll
      for (int u = 0; u < 4; u++) {
        const ulonglong2 vv = *(const ulonglong2*)&vst[(tt + u) * 132 + 4 * kg];
#pragma unroll
        for (int j = 0; j < 4; j++) {
          const float pv = (&p4[j].x)[u];
          const ull pp = pack2(pv, pv);
          ffma2(o2[j][0], pp, vv.x);
          ffma2(o2[j][1], pp, vv.y);
        }
      }
    }
    __syncthreads();
  }

  const int base = (bh * NSPLIT + split) * 16;
#pragma unroll
  for (int j = 0; j < 4; j++) {
    const int r = 4 * rg + j;
    const float2 lo = unpack2(o2[j][0]);
    const float2 hi = unpack2(o2[j][1]);
    float4 o = make_float4(lo.x, lo.y, hi.x, hi.y);
    *(float4*)&g_Op[(base + r) * cD + 4 * kg] = o;
  }
  if (kg == 0) {
#pragma unroll
    for (int j = 0; j < 4; j++) {
      g_Ms[base + 4 * rg + j] = mrun[j];
      g_Ls[base + 4 * rg + j] = lrun[j];
    }
  }
}

// ---------------------------------------------------------------------------
// Combine KV splits -> attention output buffer.
// ---------------------------------------------------------------------------
__global__ __launch_bounds__(256) void combine_kernel() {
  const int bh = blockIdx.x, tid = threadIdx.x;
  const int r = tid >> 4;
  const int dq = (tid & 15) * 8;
  const int b = bh >> 3, h = bh & 7;
  const int base = bh * NSPLIT;
  float m[NSPLIT], l[NSPLIT];
  float mstar = -1e30f;
#pragma unroll
  for (int i = 0; i < NSPLIT; i++) {
    m[i] = g_Ms[(base + i) * 16 + r];
    l[i] = g_Ls[(base + i) * 16 + r];
    mstar = fmaxf(mstar, m[i]);
  }
  float w[NSPLIT];
  float L = 0.f;
#pragma unroll
  for (int i = 0; i < NSPLIT; i++) {
    w[i] = __expf(m[i] - mstar);
    L = fmaf(w[i], l[i], L);
  }
  const float inv = 1.f / L;
  const int s = r >> 2, g = r & 3;
  float* dst = &g_ao[((b * cS + s) * cHQ + (h * 4 + g)) * cD + dq];
#pragma unroll
  for (int c2 = 0; c2 < 2; c2++) {
    float4 a = make_float4(0.f, 0.f, 0.f, 0.f);
#pragma unroll
    for (int i = 0; i < NSPLIT; i++) {
      const float4 ov = *(const float4*)&g_Op[((base + i) * 16 + r) * cD + dq + 4 * c2];
      a.x = fmaf(w[i], ov.x, a.x);
      a.y = fmaf(w[i], ov.y, a.y);
      a.z = fmaf(w[i], ov.z, a.z);
      a.w = fmaf(w[i], ov.w, a.w);
    }
    a.x *= inv; a.y *= inv; a.z *= inv; a.w *= inv;
    *(float4*)&dst[4 * c2] = a;
  }
}

// ---------------------------------------------------------------------------
__global__ __launch_bounds__(256) void sum_out_kernel(float* __restrict__ out) {
  const int i = blockIdx.x * 256 + threadIdx.x;
  if (i < cM * cNQ)
    out[i] = g_outp[0][i] + g_outp[1][i] + g_outp[2][i] + g_outp[3][i];
}

// ---------------------------------------------------------------------------
extern "C" void kernel_launch(void* const* d_in, const int* in_sizes, int n_in,
                              void* d_out, int out_size) {
  const float* x = (const float*)d_in[0];
  const float* wq = (const float*)d_in[1];
  const float* wk = (const float*)d_in[2];
  const float* wv = (const float*)d_in[3];
  const float* wo = (const float*)d_in[4];
  const float* cosb = (const float*)d_in[5];
  const float* sinb = (const float*)d_in[6];
  const float* kc = (const float*)d_in[7];
  const float* vc = (const float*)d_in[8];
  const int* pl = (const int*)d_in[9];
  float* out = (float*)d_out;

  float *qkvp, *aop, *outp;
  cudaGetSymbolAddress((void**)&qkvp, g_qkvp);
  cudaGetSymbolAddress((void**)&aop, g_ao);
  cudaGetSymbolAddress((void**)&outp, g_outp);

  // Combined QKV projection (split-K partials): 64 q-tiles + 16 k + 16 v
  gemm_f2_kernel<<<dim3(96, KSPLIT), 128>>>(x, wq, wk, wv, qkvp, 1);
  // reduce + RoPE
  rope_kernel<<<(cM * cNTOT + 255) / 256, 256>>>(cosb, sinb, pl);
  // flash-decoding attention (3-stage cp.async pipeline)
  cudaFuncSetAttribute(attn_kernel, cudaFuncAttributeMaxDynamicSharedMemorySize, ATTN_SMEM);
  attn_kernel<<<dim3(cB * cHKV, NSPLIT), 128, ATTN_SMEM>>>(kc, vc, pl);
  combine_kernel<<<cB * cHKV, 256>>>();
  // output projection
  gemm_f2_kernel<<<dim3(64, KSPLIT), 128>>>(aop, wo, wo, wo, outp, 0);
  sum_out_kernel<<<(cM * cNQ + 255) / 256, 256>>>(out);
}